// round 2
// baseline (speedup 1.0000x reference)
#include <cuda_runtime.h>
#include <math_constants.h>

#define N_NODES 100000
#define N_EDGES 1000000
#define IN_F    64
#define HEADS   4
#define OUT_C   32
#define HC      128   // HEADS*OUT_C
#define EDGE_DIM 16
#define NEG_SLOPE 0.2f

// ---------------- scratch (device globals; no allocation allowed) ----------------
__device__ float g_xproj[N_NODES * HC];        // 51.2 MB
__device__ float g_asrc[N_NODES * HEADS];
__device__ float g_adst[N_NODES * HEADS];
__device__ float g_alpha[N_EDGES * HEADS];     // 16 MB (leaky-relu'd logits)
__device__ float g_segmax[N_NODES * HEADS];
__device__ float g_denom[N_NODES * HEADS];
__device__ float g_v[EDGE_DIM * HEADS];        // folded W_edge @ att_edge
__device__ int   g_is64;                       // edge_index dtype flag

// index accessor robust to int32 vs int64 edge_index
__device__ __forceinline__ int edge_idx(const void* ei, long long elem) {
    if (g_is64) return (int)((const long long*)ei)[elem];
    return ((const int*)ei)[elem];
}

// float atomic max via ordered-int mapping (init to -inf)
__device__ __forceinline__ void atomicMaxF(float* addr, float v) {
    if (v >= 0.0f) {
        atomicMax((int*)addr, __float_as_int(v));
    } else {
        atomicMin((unsigned int*)addr, __float_as_uint(v));
    }
}

// ---------------- kernel -1: detect edge_index dtype ----------------
__global__ void k_detect(const unsigned int* __restrict__ ei_raw) {
    // If int64 little-endian with values in [0, 100000), every odd 32-bit word is 0.
    // For int32 data the odd words are random indices (P[all 64 == 0] ~ 0).
    unsigned int acc = 0;
    #pragma unroll
    for (int i = 0; i < 64; i++) acc |= ei_raw[2 * i + 1];
    g_is64 = (acc == 0u) ? 1 : 0;
}

// ---------------- kernel 0: init scratch + fold edge attention vector ----------------
__global__ void k_init(float* __restrict__ out,
                       const float* __restrict__ W_edge,
                       const float* __restrict__ att_edge) {
    int tid = blockIdx.x * blockDim.x + threadIdx.x;
    int stride = gridDim.x * blockDim.x;
    if (blockIdx.x == 0 && threadIdx.x < EDGE_DIM * HEADS) {
        int d = threadIdx.x >> 2;        // 0..15
        int h = threadIdx.x & 3;         // 0..3
        float s = 0.0f;
        #pragma unroll
        for (int c = 0; c < OUT_C; c++)
            s = fmaf(W_edge[d * HC + h * OUT_C + c], att_edge[h * OUT_C + c], s);
        g_v[d * HEADS + h] = s;
    }
    for (int i = tid; i < N_NODES * HC; i += stride) out[i] = 0.0f;
    for (int i = tid; i < N_NODES * HEADS; i += stride) {
        g_segmax[i] = -CUDART_INF_F;
        g_denom[i]  = 0.0f;
    }
}

// ---------------- kernel 1: x_proj = x @ W, plus a_src / a_dst per node ----------------
#define NODES_PER_BLOCK 64
__global__ void __launch_bounds__(128)
k_proj(const float* __restrict__ x, const float* __restrict__ W,
       const float* __restrict__ att_src, const float* __restrict__ att_dst) {
    __shared__ float Ws[IN_F * HC];     // 32 KB
    __shared__ float xs[IN_F];
    const int t = threadIdx.x;          // 0..127 -> output column
    for (int i = t; i < IN_F * HC; i += 128) Ws[i] = W[i];
    const float as = att_src[t];        // att[h = t/32][c = t%32]
    const float ad = att_dst[t];
    const int lane = t & 31;
    const int h = t >> 5;               // warp == head
    const int n0 = blockIdx.x * NODES_PER_BLOCK;
    const int n1 = min(n0 + NODES_PER_BLOCK, N_NODES);
    for (int n = n0; n < n1; n++) {
        __syncthreads();
        if (t < IN_F) xs[t] = x[n * IN_F + t];
        __syncthreads();
        float acc = 0.0f;
        #pragma unroll
        for (int k = 0; k < IN_F; k++)
            acc = fmaf(xs[k], Ws[k * HC + t], acc);
        g_xproj[n * HC + t] = acc;
        float vs = acc * as;
        float vd = acc * ad;
        #pragma unroll
        for (int o = 16; o > 0; o >>= 1) {
            vs += __shfl_down_sync(0xffffffffu, vs, o);
            vd += __shfl_down_sync(0xffffffffu, vd, o);
        }
        if (lane == 0) {
            g_asrc[n * HEADS + h] = vs;
            g_adst[n * HEADS + h] = vd;
        }
    }
}

// ---------------- kernel 2: per-edge logits + leaky-relu + segment max ----------------
__global__ void k_edgeA(const void* __restrict__ ei,
                        const float* __restrict__ edge_attr) {
    int e = blockIdx.x * blockDim.x + threadIdx.x;
    if (e >= N_EDGES) return;
    const int src = edge_idx(ei, e);
    const int dst = edge_idx(ei, (long long)N_EDGES + e);

    // load edge_attr row (16 floats, vectorized)
    const float4* eap = (const float4*)(edge_attr + (size_t)e * EDGE_DIM);
    float ea[EDGE_DIM];
    #pragma unroll
    for (int q = 0; q < 4; q++) {
        float4 v = eap[q];
        ea[q * 4 + 0] = v.x; ea[q * 4 + 1] = v.y;
        ea[q * 4 + 2] = v.z; ea[q * 4 + 3] = v.w;
    }
    const float4 asv = *(const float4*)(g_asrc + src * HEADS);
    const float4 adv = *(const float4*)(g_adst + dst * HEADS);
    float base[HEADS] = {asv.x + adv.x, asv.y + adv.y, asv.z + adv.z, asv.w + adv.w};

    float al[HEADS];
    #pragma unroll
    for (int h = 0; h < HEADS; h++) {
        float s = base[h];
        #pragma unroll
        for (int d = 0; d < EDGE_DIM; d++)
            s = fmaf(ea[d], g_v[d * HEADS + h], s);
        // leaky relu
        s = (s >= 0.0f) ? s : s * NEG_SLOPE;
        al[h] = s;
        atomicMaxF(&g_segmax[dst * HEADS + h], s);
    }
    *(float4*)(g_alpha + (size_t)e * HEADS) = make_float4(al[0], al[1], al[2], al[3]);
}

// ---------------- kernel 3: w = exp(alpha - max); scatter w*x_proj[src] and denom ----------------
__global__ void __launch_bounds__(256)
k_edgeB(const void* __restrict__ ei, float* __restrict__ out) {
    const int gw = (blockIdx.x * blockDim.x + threadIdx.x) >> 5;   // warp id == edge
    const int lane = threadIdx.x & 31;
    if (gw >= N_EDGES) return;
    const int e = gw;
    const int src = edge_idx(ei, e);
    const int dst = edge_idx(ei, (long long)N_EDGES + e);
    const int h = lane >> 3;                                        // 8 lanes per head

    const float a  = __ldg(g_alpha + (size_t)e * HEADS + h);
    const float mx = __ldg(g_segmax + dst * HEADS + h);
    const float w  = __expf(a - mx);

    if ((lane & 7) == 0)
        atomicAdd(&g_denom[dst * HEADS + h], w);

    const float4 v = *(const float4*)(g_xproj + (size_t)src * HC + lane * 4);
    float* o = out + (size_t)dst * HC + lane * 4;
    atomicAdd(o + 0, v.x * w);
    atomicAdd(o + 1, v.y * w);
    atomicAdd(o + 2, v.z * w);
    atomicAdd(o + 3, v.w * w);
}

// ---------------- kernel 4: normalize + bias ----------------
__global__ void k_fin(float* __restrict__ out, const float* __restrict__ bias) {
    int i = blockIdx.x * blockDim.x + threadIdx.x;
    if (i >= N_NODES * HC) return;
    const int n = i >> 7;
    const int col = i & 127;
    const int h = col >> 5;
    out[i] = out[i] / (g_denom[n * HEADS + h] + 1e-16f) + bias[col];
}

// ---------------- launch ----------------
extern "C" void kernel_launch(void* const* d_in, const int* in_sizes, int n_in,
                              void* d_out, int out_size) {
    const float* x         = (const float*)d_in[0];
    const void*  ei        = d_in[1];
    const float* edge_attr = (const float*)d_in[2];
    const float* W         = (const float*)d_in[3];
    const float* W_edge    = (const float*)d_in[4];
    const float* att_src   = (const float*)d_in[5];
    const float* att_dst   = (const float*)d_in[6];
    const float* att_edge  = (const float*)d_in[7];
    const float* bias      = (const float*)d_in[8];
    float* out = (float*)d_out;

    k_detect<<<1, 1>>>((const unsigned int*)ei);

    k_init<<<2048, 256>>>(out, W_edge, att_edge);

    k_proj<<<(N_NODES + NODES_PER_BLOCK - 1) / NODES_PER_BLOCK, 128>>>(x, W, att_src, att_dst);

    k_edgeA<<<(N_EDGES + 255) / 256, 256>>>(ei, edge_attr);

    // one warp per edge
    k_edgeB<<<(N_EDGES * 32 + 255) / 256, 256>>>(ei, out);

    k_fin<<<(N_NODES * HC + 255) / 256, 256>>>(out, bias);
}

// round 3
// speedup vs baseline: 1.9046x; 1.9046x over previous
#include <cuda_runtime.h>
#include <math_constants.h>

#define N_NODES 100000
#define N_EDGES 1000000
#define IN_F    64
#define HEADS   4
#define OUT_C   32
#define HC      128   // HEADS*OUT_C
#define EDGE_DIM 16
#define NEG_SLOPE 0.2f

// ---------------- scratch (device globals; no allocation allowed) ----------------
__device__ float g_xproj[N_NODES * HC];        // 51.2 MB (L2-resident table)
__device__ float g_asrc[N_NODES * HEADS];
__device__ float g_adst[N_NODES * HEADS];
__device__ float g_alpha[N_EDGES * HEADS];     // 16 MB (leaky-relu'd logits)
__device__ float g_segmax[N_NODES * HEADS];
__device__ float g_denom[N_NODES * HEADS];
__device__ float g_v[EDGE_DIM * HEADS];        // folded W_edge @ att_edge
__device__ float g_u[IN_F * 8];                // folded W @ att_src|att_dst  [d][j], j<4 src, j>=4 dst
__device__ int   g_is64;                       // edge_index dtype flag

// index accessor robust to int32 vs int64 edge_index
__device__ __forceinline__ int edge_idx(const void* ei, long long elem) {
    if (g_is64) return (int)((const long long*)ei)[elem];
    return ((const int*)ei)[elem];
}

// float atomic max via ordered-int mapping (init to -inf)
__device__ __forceinline__ void atomicMaxF(float* addr, float v) {
    if (v >= 0.0f) {
        atomicMax((int*)addr, __float_as_int(v));
    } else {
        atomicMin((unsigned int*)addr, __float_as_uint(v));
    }
}

// ---------------- kernel -1: detect edge_index dtype ----------------
__global__ void k_detect(const unsigned int* __restrict__ ei_raw) {
    unsigned int acc = 0;
    #pragma unroll
    for (int i = 0; i < 64; i++) acc |= ei_raw[2 * i + 1];
    g_is64 = (acc == 0u) ? 1 : 0;
}

// ---------------- kernel 0: init scratch + fold attention vectors ----------------
__global__ void k_init(float* __restrict__ out,
                       const float* __restrict__ W,
                       const float* __restrict__ W_edge,
                       const float* __restrict__ att_src,
                       const float* __restrict__ att_dst,
                       const float* __restrict__ att_edge) {
    int tid = blockIdx.x * blockDim.x + threadIdx.x;
    int stride = gridDim.x * blockDim.x;
    if (blockIdx.x == 0) {
        // g_v: [16][4]
        for (int i = threadIdx.x; i < EDGE_DIM * HEADS; i += blockDim.x) {
            int d = i >> 2, h = i & 3;
            float s = 0.0f;
            #pragma unroll
            for (int c = 0; c < OUT_C; c++)
                s = fmaf(W_edge[d * HC + h * OUT_C + c], att_edge[h * OUT_C + c], s);
            g_v[d * HEADS + h] = s;
        }
        // g_u: [64][8]
        for (int i = threadIdx.x; i < IN_F * 8; i += blockDim.x) {
            int d = i >> 3, j = i & 7;
            int h = j & 3;
            const float* att = (j < 4) ? att_src : att_dst;
            float s = 0.0f;
            #pragma unroll
            for (int c = 0; c < OUT_C; c++)
                s = fmaf(W[d * HC + h * OUT_C + c], att[h * OUT_C + c], s);
            g_u[d * 8 + j] = s;
        }
    }
    float4* outv = (float4*)out;
    for (int i = tid; i < (N_NODES * HC) / 4; i += stride)
        outv[i] = make_float4(0.f, 0.f, 0.f, 0.f);
    for (int i = tid; i < N_NODES * HEADS; i += stride) {
        g_segmax[i] = -CUDART_INF_F;
        g_denom[i]  = 0.0f;
    }
}

// ---------------- kernel 1: x_proj = x @ W  (128x128 tile, 8x8 micro-tile) ----------------
#define KSLAB 32
__global__ void __launch_bounds__(256, 2)
k_proj(const float* __restrict__ x, const float* __restrict__ W) {
    __shared__ float As[KSLAB * 128];   // As[k][m]  16 KB
    __shared__ float Bs[KSLAB * 128];   // Bs[k][n]  16 KB
    const int t  = threadIdx.x;
    const int tx = t & 15;              // n-block
    const int ty = t >> 4;              // m-block
    const int m0 = blockIdx.x * 128;

    float acc[8][8];
    #pragma unroll
    for (int i = 0; i < 8; i++)
        #pragma unroll
        for (int j = 0; j < 8; j++) acc[i][j] = 0.0f;

    for (int slab = 0; slab < IN_F; slab += KSLAB) {
        // load As: 128 nodes x 32 k. 1024 float4s; m = f&127, kq = f>>7 (conflict-free STS)
        #pragma unroll
        for (int r = 0; r < 4; r++) {
            int f = r * 256 + t;
            int m = f & 127;
            int kq = f >> 7;            // 0..7
            int node = m0 + m;
            float4 v = make_float4(0.f, 0.f, 0.f, 0.f);
            if (node < N_NODES)
                v = *(const float4*)(x + (size_t)node * IN_F + slab + kq * 4);
            As[(kq * 4 + 0) * 128 + m] = v.x;
            As[(kq * 4 + 1) * 128 + m] = v.y;
            As[(kq * 4 + 2) * 128 + m] = v.z;
            As[(kq * 4 + 3) * 128 + m] = v.w;
        }
        // load Bs: 32 k x 128 n. f4: n4 = f&31, k = f>>5 (coalesced, conflict-free)
        #pragma unroll
        for (int r = 0; r < 4; r++) {
            int f = r * 256 + t;
            int n4 = f & 31;
            int k  = f >> 5;
            *(float4*)(Bs + k * 128 + n4 * 4) =
                *(const float4*)(W + (size_t)(slab + k) * HC + n4 * 4);
        }
        __syncthreads();
        #pragma unroll
        for (int k = 0; k < KSLAB; k++) {
            float a[8], b[8];
            *(float4*)(a)     = *(const float4*)(As + k * 128 + ty * 8);
            *(float4*)(a + 4) = *(const float4*)(As + k * 128 + ty * 8 + 4);
            *(float4*)(b)     = *(const float4*)(Bs + k * 128 + tx * 8);
            *(float4*)(b + 4) = *(const float4*)(Bs + k * 128 + tx * 8 + 4);
            #pragma unroll
            for (int i = 0; i < 8; i++)
                #pragma unroll
                for (int j = 0; j < 8; j++)
                    acc[i][j] = fmaf(a[i], b[j], acc[i][j]);
        }
        __syncthreads();
    }
    // epilogue
    #pragma unroll
    for (int i = 0; i < 8; i++) {
        int node = m0 + ty * 8 + i;
        if (node < N_NODES) {
            float* dst = g_xproj + (size_t)node * HC + tx * 8;
            *(float4*)(dst)     = make_float4(acc[i][0], acc[i][1], acc[i][2], acc[i][3]);
            *(float4*)(dst + 4) = make_float4(acc[i][4], acc[i][5], acc[i][6], acc[i][7]);
        }
    }
}

// ---------------- kernel 2: a_src / a_dst = x @ g_u ----------------
__global__ void __launch_bounds__(128)
k_att(const float* __restrict__ x) {
    __shared__ float xs[16 * IN_F];   // 4 KB
    __shared__ float us[IN_F * 8];    // 2 KB
    const int t = threadIdx.x;
    for (int i = t; i < IN_F * 8; i += 128) us[i] = g_u[i];
    const int n0 = blockIdx.x * 16;   // N_NODES = 16*6250 exactly
    const float4* xp = (const float4*)(x + (size_t)n0 * IN_F);
    float4* xsp = (float4*)xs;
    #pragma unroll
    for (int r = 0; r < 2; r++) xsp[r * 128 + t] = xp[r * 128 + t];
    __syncthreads();
    const int n = t >> 3, j = t & 7;
    float s = 0.0f;
    #pragma unroll
    for (int d = 0; d < IN_F; d++)
        s = fmaf(xs[n * IN_F + d], us[d * 8 + j], s);
    const int node = n0 + n;
    if (j < 4) g_asrc[node * HEADS + j] = s;
    else       g_adst[node * HEADS + (j - 4)] = s;
}

// ---------------- kernel 3: per-edge logits + leaky-relu + segment max ----------------
__global__ void k_edgeA(const void* __restrict__ ei,
                        const float* __restrict__ edge_attr) {
    int e = blockIdx.x * blockDim.x + threadIdx.x;
    if (e >= N_EDGES) return;
    const int src = edge_idx(ei, e);
    const int dst = edge_idx(ei, (long long)N_EDGES + e);

    const float4* eap = (const float4*)(edge_attr + (size_t)e * EDGE_DIM);
    float ea[EDGE_DIM];
    #pragma unroll
    for (int q = 0; q < 4; q++) {
        float4 v = eap[q];
        ea[q * 4 + 0] = v.x; ea[q * 4 + 1] = v.y;
        ea[q * 4 + 2] = v.z; ea[q * 4 + 3] = v.w;
    }
    const float4 asv = *(const float4*)(g_asrc + src * HEADS);
    const float4 adv = *(const float4*)(g_adst + dst * HEADS);
    float base[HEADS] = {asv.x + adv.x, asv.y + adv.y, asv.z + adv.z, asv.w + adv.w};

    float al[HEADS];
    #pragma unroll
    for (int h = 0; h < HEADS; h++) {
        float s = base[h];
        #pragma unroll
        for (int d = 0; d < EDGE_DIM; d++)
            s = fmaf(ea[d], g_v[d * HEADS + h], s);
        s = (s >= 0.0f) ? s : s * NEG_SLOPE;
        al[h] = s;
        atomicMaxF(&g_segmax[dst * HEADS + h], s);
    }
    *(float4*)(g_alpha + (size_t)e * HEADS) = make_float4(al[0], al[1], al[2], al[3]);
}

// ---------------- kernel 4: w = exp(alpha-max); vectorized red scatter ----------------
__global__ void __launch_bounds__(256)
k_edgeB(const void* __restrict__ ei, float* __restrict__ out) {
    const int gw = (blockIdx.x * blockDim.x + threadIdx.x) >> 5;   // warp == edge
    const int lane = threadIdx.x & 31;
    if (gw >= N_EDGES) return;
    const int src = edge_idx(ei, gw);
    const int dst = edge_idx(ei, (long long)N_EDGES + gw);
    const int h = lane >> 3;                                       // 8 lanes per head

    const float a  = __ldg(g_alpha + (size_t)gw * HEADS + h);
    const float mx = __ldg(g_segmax + dst * HEADS + h);
    const float w  = __expf(a - mx);

    if ((lane & 7) == 0)
        asm volatile("red.global.add.f32 [%0], %1;"
                     :: "l"(g_denom + dst * HEADS + h), "f"(w) : "memory");

    const float4 v = *(const float4*)(g_xproj + (size_t)src * HC + lane * 4);
    float* o = out + (size_t)dst * HC + lane * 4;
    asm volatile("red.global.add.v4.f32 [%0], {%1, %2, %3, %4};"
                 :: "l"(o), "f"(v.x * w), "f"(v.y * w), "f"(v.z * w), "f"(v.w * w)
                 : "memory");
}

// ---------------- kernel 5: normalize + bias ----------------
__global__ void k_fin(float* __restrict__ out, const float* __restrict__ bias) {
    int i4 = blockIdx.x * blockDim.x + threadIdx.x;          // float4 index
    if (i4 >= (N_NODES * HC) / 4) return;
    const int n = i4 >> 5;            // 32 float4 per node
    const int cq = i4 & 31;           // float4-col
    const int h = cq >> 3;
    const float d = g_denom[n * HEADS + h] + 1e-16f;
    const float inv = 1.0f / d;
    float4 v = ((float4*)out)[i4];
    const float4 b = ((const float4*)bias)[cq];
    v.x = v.x * inv + b.x; v.y = v.y * inv + b.y;
    v.z = v.z * inv + b.z; v.w = v.w * inv + b.w;
    ((float4*)out)[i4] = v;
}

// ---------------- launch ----------------
extern "C" void kernel_launch(void* const* d_in, const int* in_sizes, int n_in,
                              void* d_out, int out_size) {
    const float* x         = (const float*)d_in[0];
    const void*  ei        = d_in[1];
    const float* edge_attr = (const float*)d_in[2];
    const float* W         = (const float*)d_in[3];
    const float* W_edge    = (const float*)d_in[4];
    const float* att_src   = (const float*)d_in[5];
    const float* att_dst   = (const float*)d_in[6];
    const float* att_edge  = (const float*)d_in[7];
    const float* bias      = (const float*)d_in[8];
    float* out = (float*)d_out;

    k_detect<<<1, 1>>>((const unsigned int*)ei);
    k_init<<<2048, 256>>>(out, W, W_edge, att_src, att_dst, att_edge);
    k_proj<<<(N_NODES + 127) / 128, 256>>>(x, W);
    k_att<<<N_NODES / 16, 128>>>(x);
    k_edgeA<<<(N_EDGES + 255) / 256, 256>>>(ei, edge_attr);
    k_edgeB<<<(N_EDGES * 32 + 255) / 256, 256>>>(ei, out);
    k_fin<<<((N_NODES * HC) / 4 + 255) / 256, 256>>>(out, bias);
}

// round 4
// speedup vs baseline: 2.8197x; 1.4805x over previous
#include <cuda_runtime.h>
#include <math_constants.h>

#define N_NODES 100000
#define N_EDGES 1000000
#define IN_F    64
#define HEADS   4
#define OUT_C   32
#define HC      128   // HEADS*OUT_C
#define EDGE_DIM 16
#define NEG_SLOPE 0.2f

#define SCAN_BLK 512
#define SCAN_NB  ((N_NODES + SCAN_BLK - 1) / SCAN_BLK)   // 196

// ---------------- scratch (device globals; no allocation allowed) ----------------
__device__ __align__(16) float g_xproj[N_NODES * HC];      // 51.2 MB (L2-resident table)
__device__ __align__(16) float g_alpha[N_EDGES * HEADS];   // 16 MB logits (edge order)
__device__ __align__(16) float g_csr_alpha[N_EDGES * HEADS]; // 16 MB logits (CSR order)
__device__ float g_asrc[N_NODES * HEADS];
__device__ float g_adst[N_NODES * HEADS];
__device__ int   g_csr_src[N_EDGES];
__device__ int   g_count[N_NODES];
__device__ int   g_node_start[N_NODES + 1];
__device__ int   g_cursor[N_NODES];
__device__ int   g_bsum[SCAN_NB];
__device__ int   g_boff[SCAN_NB];
__device__ float g_v[EDGE_DIM * HEADS];        // folded W_edge @ att_edge
__device__ int   g_is64;                       // edge_index dtype flag

// index accessor robust to int32 vs int64 edge_index
__device__ __forceinline__ int edge_idx(const void* ei, long long elem) {
    if (g_is64) return (int)((const long long*)ei)[elem];
    return ((const int*)ei)[elem];
}

// ---------------- kernel -1: detect edge_index dtype ----------------
__global__ void k_detect(const unsigned int* __restrict__ ei_raw) {
    unsigned int acc = 0;
    #pragma unroll
    for (int i = 0; i < 64; i++) acc |= ei_raw[2 * i + 1];
    g_is64 = (acc == 0u) ? 1 : 0;
}

// ---------------- kernel 0: zero counts + fold edge attention vector ----------------
__global__ void k_init(const float* __restrict__ W_edge,
                       const float* __restrict__ att_edge) {
    int tid = blockIdx.x * blockDim.x + threadIdx.x;
    int stride = gridDim.x * blockDim.x;
    if (blockIdx.x == 0) {
        for (int i = threadIdx.x; i < EDGE_DIM * HEADS; i += blockDim.x) {
            int d = i >> 2, h = i & 3;
            float s = 0.0f;
            #pragma unroll
            for (int c = 0; c < OUT_C; c++)
                s = fmaf(W_edge[d * HC + h * OUT_C + c], att_edge[h * OUT_C + c], s);
            g_v[d * HEADS + h] = s;
        }
    }
    for (int i = tid; i < N_NODES; i += stride) g_count[i] = 0;
}

// ---------------- kernel 1: x_proj = x @ W + fused a_src/a_dst epilogue ----------------
#define KSLAB 32
__global__ void __launch_bounds__(256, 2)
k_proj(const float* __restrict__ x, const float* __restrict__ W,
       const float* __restrict__ att_src, const float* __restrict__ att_dst) {
    __shared__ float As[KSLAB * 128];   // As[k][m]
    __shared__ float Bs[KSLAB * 128];   // Bs[k][n]
    const int t  = threadIdx.x;
    const int tx = t & 15;              // n-block (cols tx*8..tx*8+7, head = tx>>2)
    const int ty = t >> 4;              // m-block
    const int m0 = blockIdx.x * 128;

    float acc[8][8];
    #pragma unroll
    for (int i = 0; i < 8; i++)
        #pragma unroll
        for (int j = 0; j < 8; j++) acc[i][j] = 0.0f;

    for (int slab = 0; slab < IN_F; slab += KSLAB) {
        #pragma unroll
        for (int r = 0; r < 4; r++) {
            int f = r * 256 + t;
            int m = f & 127;
            int kq = f >> 7;
            int node = m0 + m;
            float4 v = make_float4(0.f, 0.f, 0.f, 0.f);
            if (node < N_NODES)
                v = *(const float4*)(x + (size_t)node * IN_F + slab + kq * 4);
            As[(kq * 4 + 0) * 128 + m] = v.x;
            As[(kq * 4 + 1) * 128 + m] = v.y;
            As[(kq * 4 + 2) * 128 + m] = v.z;
            As[(kq * 4 + 3) * 128 + m] = v.w;
        }
        #pragma unroll
        for (int r = 0; r < 4; r++) {
            int f = r * 256 + t;
            int n4 = f & 31;
            int k  = f >> 5;
            *(float4*)(Bs + k * 128 + n4 * 4) =
                *(const float4*)(W + (size_t)(slab + k) * HC + n4 * 4);
        }
        __syncthreads();
        #pragma unroll
        for (int k = 0; k < KSLAB; k++) {
            float a[8], b[8];
            *(float4*)(a)     = *(const float4*)(As + k * 128 + ty * 8);
            *(float4*)(a + 4) = *(const float4*)(As + k * 128 + ty * 8 + 4);
            *(float4*)(b)     = *(const float4*)(Bs + k * 128 + tx * 8);
            *(float4*)(b + 4) = *(const float4*)(Bs + k * 128 + tx * 8 + 4);
            #pragma unroll
            for (int i = 0; i < 8; i++)
                #pragma unroll
                for (int j = 0; j < 8; j++)
                    acc[i][j] = fmaf(a[i], b[j], acc[i][j]);
        }
        __syncthreads();
    }

    // attention fold vectors for this thread's 8 columns
    float as[8], ad[8];
    *(float4*)(as)     = *(const float4*)(att_src + tx * 8);
    *(float4*)(as + 4) = *(const float4*)(att_src + tx * 8 + 4);
    *(float4*)(ad)     = *(const float4*)(att_dst + tx * 8);
    *(float4*)(ad + 4) = *(const float4*)(att_dst + tx * 8 + 4);
    const int h = tx >> 2;

    #pragma unroll
    for (int i = 0; i < 8; i++) {
        int node = m0 + ty * 8 + i;
        float ps = 0.f, pd = 0.f;
        #pragma unroll
        for (int j = 0; j < 8; j++) {
            ps = fmaf(acc[i][j], as[j], ps);
            pd = fmaf(acc[i][j], ad[j], pd);
        }
        // reduce over the 4 lanes sharing one head (lane bits 0..1 == tx bits 0..1)
        ps += __shfl_xor_sync(0xffffffffu, ps, 1);
        ps += __shfl_xor_sync(0xffffffffu, ps, 2);
        pd += __shfl_xor_sync(0xffffffffu, pd, 1);
        pd += __shfl_xor_sync(0xffffffffu, pd, 2);
        if (node < N_NODES) {
            float* dst = g_xproj + (size_t)node * HC + tx * 8;
            *(float4*)(dst)     = make_float4(acc[i][0], acc[i][1], acc[i][2], acc[i][3]);
            *(float4*)(dst + 4) = make_float4(acc[i][4], acc[i][5], acc[i][6], acc[i][7]);
            if ((tx & 3) == 0) {
                g_asrc[node * HEADS + h] = ps;
                g_adst[node * HEADS + h] = pd;
            }
        }
    }
}

// ---------------- kernel 2: per-edge logits + leaky-relu + dst histogram ----------------
__global__ void k_edgeA(const void* __restrict__ ei,
                        const float* __restrict__ edge_attr) {
    int e = blockIdx.x * blockDim.x + threadIdx.x;
    if (e >= N_EDGES) return;
    const int src = edge_idx(ei, e);
    const int dst = edge_idx(ei, (long long)N_EDGES + e);

    const float4* eap = (const float4*)(edge_attr + (size_t)e * EDGE_DIM);
    float ea[EDGE_DIM];
    #pragma unroll
    for (int q = 0; q < 4; q++) {
        float4 v = eap[q];
        ea[q * 4 + 0] = v.x; ea[q * 4 + 1] = v.y;
        ea[q * 4 + 2] = v.z; ea[q * 4 + 3] = v.w;
    }
    const float4 asv = *(const float4*)(g_asrc + src * HEADS);
    const float4 adv = *(const float4*)(g_adst + dst * HEADS);
    float base[HEADS] = {asv.x + adv.x, asv.y + adv.y, asv.z + adv.z, asv.w + adv.w};

    float al[HEADS];
    #pragma unroll
    for (int h = 0; h < HEADS; h++) {
        float s = base[h];
        #pragma unroll
        for (int d = 0; d < EDGE_DIM; d++)
            s = fmaf(ea[d], g_v[d * HEADS + h], s);
        al[h] = (s >= 0.0f) ? s : s * NEG_SLOPE;
    }
    *(float4*)(g_alpha + (size_t)e * HEADS) = make_float4(al[0], al[1], al[2], al[3]);
    atomicAdd(&g_count[dst], 1);
}

// ---------------- scan kernels: exclusive prefix over g_count ----------------
__global__ void __launch_bounds__(SCAN_BLK) k_scan1() {
    __shared__ int s[SCAN_BLK];
    int i = blockIdx.x * SCAN_BLK + threadIdx.x;
    s[threadIdx.x] = (i < N_NODES) ? g_count[i] : 0;
    __syncthreads();
    for (int off = SCAN_BLK / 2; off > 0; off >>= 1) {
        if (threadIdx.x < off) s[threadIdx.x] += s[threadIdx.x + off];
        __syncthreads();
    }
    if (threadIdx.x == 0) g_bsum[blockIdx.x] = s[0];
}

__global__ void k_scan2() {
    __shared__ int s[SCAN_NB];
    if (threadIdx.x < SCAN_NB) s[threadIdx.x] = g_bsum[threadIdx.x];
    __syncthreads();
    if (threadIdx.x == 0) {
        int run = 0;
        for (int b = 0; b < SCAN_NB; b++) { g_boff[b] = run; run += s[b]; }
    }
}

__global__ void __launch_bounds__(SCAN_BLK) k_scan3() {
    __shared__ int s[SCAN_BLK];
    int i = blockIdx.x * SCAN_BLK + threadIdx.x;
    int c = (i < N_NODES) ? g_count[i] : 0;
    s[threadIdx.x] = c;
    __syncthreads();
    // Hillis-Steele inclusive scan
    for (int off = 1; off < SCAN_BLK; off <<= 1) {
        int v = (threadIdx.x >= off) ? s[threadIdx.x - off] : 0;
        __syncthreads();
        s[threadIdx.x] += v;
        __syncthreads();
    }
    if (i < N_NODES) {
        int start = g_boff[blockIdx.x] + s[threadIdx.x] - c;   // exclusive
        g_node_start[i] = start;
        g_cursor[i]     = start;
    }
    if (blockIdx.x == 0 && threadIdx.x == 0) g_node_start[N_NODES] = N_EDGES;
}

// ---------------- kernel 3: scatter edges into CSR order ----------------
__global__ void k_place(const void* __restrict__ ei) {
    int e = blockIdx.x * blockDim.x + threadIdx.x;
    if (e >= N_EDGES) return;
    const int src = edge_idx(ei, e);
    const int dst = edge_idx(ei, (long long)N_EDGES + e);
    int pos = atomicAdd(&g_cursor[dst], 1);
    g_csr_src[pos] = src;
    *(float4*)(g_csr_alpha + (size_t)pos * HEADS) =
        *(const float4*)(g_alpha + (size_t)e * HEADS);
}

// ---------------- kernel 4: fused softmax + gather + normalize + bias ----------------
__global__ void __launch_bounds__(256)
k_fused(float* __restrict__ out, const float* __restrict__ bias) {
    __shared__ float sw[8][32][4];     // per-warp edge weights [edge-in-chunk][head]
    const int warp = threadIdx.x >> 5;
    const int lane = threadIdx.x & 31;
    const int n = blockIdx.x * 8 + warp;
    if (n >= N_NODES) return;
    const int s0 = g_node_start[n];
    const int deg = g_node_start[n + 1] - s0;
    const int h = lane >> 3;                    // lane's head (4 channels each)
    const float4 b4 = ((const float4*)bias)[lane];

    if (deg == 0) { ((float4*)out)[(size_t)n * 32 + lane] = b4; return; }

    // pass 1: per-head max over this node's edges
    float4 mx = make_float4(-CUDART_INF_F, -CUDART_INF_F, -CUDART_INF_F, -CUDART_INF_F);
    for (int base = 0; base < deg; base += 32) {
        int k = base + lane;
        if (k < deg) {
            float4 a = *(const float4*)(g_csr_alpha + (size_t)(s0 + k) * HEADS);
            mx.x = fmaxf(mx.x, a.x); mx.y = fmaxf(mx.y, a.y);
            mx.z = fmaxf(mx.z, a.z); mx.w = fmaxf(mx.w, a.w);
        }
    }
    #pragma unroll
    for (int off = 16; off > 0; off >>= 1) {
        mx.x = fmaxf(mx.x, __shfl_xor_sync(0xffffffffu, mx.x, off));
        mx.y = fmaxf(mx.y, __shfl_xor_sync(0xffffffffu, mx.y, off));
        mx.z = fmaxf(mx.z, __shfl_xor_sync(0xffffffffu, mx.z, off));
        mx.w = fmaxf(mx.w, __shfl_xor_sync(0xffffffffu, mx.w, off));
    }

    // pass 2: weights, denom, gather-accumulate
    float4 acc  = make_float4(0.f, 0.f, 0.f, 0.f);
    float4 dsum = make_float4(0.f, 0.f, 0.f, 0.f);
    for (int base = 0; base < deg; base += 32) {
        int k = base + lane;
        int cnt = min(32, deg - base);
        float4 w4 = make_float4(0.f, 0.f, 0.f, 0.f);
        int srcj = 0;
        if (k < deg) {
            float4 a = *(const float4*)(g_csr_alpha + (size_t)(s0 + k) * HEADS);
            w4.x = __expf(a.x - mx.x); w4.y = __expf(a.y - mx.y);
            w4.z = __expf(a.z - mx.z); w4.w = __expf(a.w - mx.w);
            srcj = g_csr_src[s0 + k];
            dsum.x += w4.x; dsum.y += w4.y; dsum.z += w4.z; dsum.w += w4.w;
        }
        *(float4*)(&sw[warp][lane][0]) = w4;
        __syncwarp();
        for (int j = 0; j < cnt; j++) {
            int src  = __shfl_sync(0xffffffffu, srcj, j);
            float wj = sw[warp][j][h];
            float4 v = *(const float4*)(g_xproj + (size_t)src * HC + lane * 4);
            acc.x = fmaf(v.x, wj, acc.x);
            acc.y = fmaf(v.y, wj, acc.y);
            acc.z = fmaf(v.z, wj, acc.z);
            acc.w = fmaf(v.w, wj, acc.w);
        }
        __syncwarp();
    }
    #pragma unroll
    for (int off = 16; off > 0; off >>= 1) {
        dsum.x += __shfl_xor_sync(0xffffffffu, dsum.x, off);
        dsum.y += __shfl_xor_sync(0xffffffffu, dsum.y, off);
        dsum.z += __shfl_xor_sync(0xffffffffu, dsum.z, off);
        dsum.w += __shfl_xor_sync(0xffffffffu, dsum.w, off);
    }
    float den = (h == 0) ? dsum.x : (h == 1) ? dsum.y : (h == 2) ? dsum.z : dsum.w;
    float inv = 1.0f / (den + 1e-16f);
    float4 o;
    o.x = fmaf(acc.x, inv, b4.x); o.y = fmaf(acc.y, inv, b4.y);
    o.z = fmaf(acc.z, inv, b4.z); o.w = fmaf(acc.w, inv, b4.w);
    ((float4*)out)[(size_t)n * 32 + lane] = o;
}

// ---------------- launch ----------------
extern "C" void kernel_launch(void* const* d_in, const int* in_sizes, int n_in,
                              void* d_out, int out_size) {
    const float* x         = (const float*)d_in[0];
    const void*  ei        = d_in[1];
    const float* edge_attr = (const float*)d_in[2];
    const float* W         = (const float*)d_in[3];
    const float* W_edge    = (const float*)d_in[4];
    const float* att_src   = (const float*)d_in[5];
    const float* att_dst   = (const float*)d_in[6];
    const float* att_edge  = (const float*)d_in[7];
    const float* bias      = (const float*)d_in[8];
    float* out = (float*)d_out;

    k_detect<<<1, 1>>>((const unsigned int*)ei);
    k_init<<<256, 256>>>(W_edge, att_edge);
    k_proj<<<(N_NODES + 127) / 128, 256>>>(x, W, att_src, att_dst);
    k_edgeA<<<(N_EDGES + 255) / 256, 256>>>(ei, edge_attr);
    k_scan1<<<SCAN_NB, SCAN_BLK>>>();
    k_scan2<<<1, 256>>>();
    k_scan3<<<SCAN_NB, SCAN_BLK>>>();
    k_place<<<(N_EDGES + 255) / 256, 256>>>(ei);
    k_fused<<<(N_NODES + 7) / 8, 256>>>(out, bias);
}